// round 9
// baseline (speedup 1.0000x reference)
#include <cuda_runtime.h>
#include <cuda_fp16.h>

#define BATCH 64
#define MM 512
#define NN 512
#define DH 64
#define NDIAG (MM + NN - 1)   /* 1023 */
#define BIGF 1e10f
#define SCALE_EX2 14.4269504088896f   /* (1/gamma) * log2(e), gamma = 0.1 */
#define GLN2 0.0693147180559945f      /* gamma * ln(2) */
#define POISON 0x7FBFFFFFu            /* NaN pattern never produced by the DP */

// Diagonal-major distance matrix, fp16: Ddiag[b][(i+j)][i] = D[b][i][j]
__device__ __half g_Ddiag[(size_t)BATCH * NDIAG * MM];
__device__ float g_perbatch[BATCH];

__device__ __forceinline__ float ex2f(float x) {
    float r; asm("ex2.approx.ftz.f32 %0, %1;" : "=f"(r) : "f"(x)); return r;
}
__device__ __forceinline__ float lg2f(float x) {
    float r; asm("lg2.approx.ftz.f32 %0, %1;" : "=f"(r) : "f"(x)); return r;
}
__device__ __forceinline__ unsigned long long pk2(float lo, float hi) {
    unsigned long long p;
    asm("mov.b64 %0, {%1, %2};" : "=l"(p) : "f"(lo), "f"(hi));
    return p;
}
__device__ __forceinline__ void fma2(unsigned long long& acc,
                                     unsigned long long a, unsigned long long b) {
    asm("fma.rn.f32x2 %0, %1, %2, %0;" : "+l"(acc) : "l"(a), "l"(b));
}
__device__ __forceinline__ void upk2(unsigned long long p, float& lo, float& hi) {
    asm("mov.b64 {%0, %1}, %2;" : "=f"(lo), "=f"(hi) : "l"(p));
}

// ---------------------------------------------------------------------------
// Kernel 1: pairwise squared L2 -> diagonal-major fp16.  (unchanged, 94us)
// Grid (8,8,64), 256 threads. 4x4 microtile with interleaved columns,
// stride-65 smem, hoisted norms, packed f32x2 FMA (SASS FFMA2).
// ---------------------------------------------------------------------------
__global__ __launch_bounds__(256) void pairwise_diag_kernel(
    const float* __restrict__ x, const float* __restrict__ y)
{
    __shared__ float xs[64][65];
    __shared__ float ys[64][65];
    __shared__ float Cs[64][66];
    __shared__ float xn[64], yn[64];

    int b  = blockIdx.z;
    int i0 = blockIdx.y * 64;
    int j0 = blockIdx.x * 64;
    int tid = threadIdx.x;

    const float* xb = x + ((size_t)b * MM + i0) * DH;
    const float* yb = y + ((size_t)b * NN + j0) * DH;

    #pragma unroll
    for (int e = tid; e < 1024; e += 256) {
        int r = e >> 4, c = (e & 15) * 4;
        float4 vx = *(const float4*)&xb[r * DH + c];
        float4 vy = *(const float4*)&yb[r * DH + c];
        xs[r][c] = vx.x; xs[r][c+1] = vx.y; xs[r][c+2] = vx.z; xs[r][c+3] = vx.w;
        ys[r][c] = vy.x; ys[r][c+1] = vy.y; ys[r][c+2] = vy.z; ys[r][c+3] = vy.w;
    }
    __syncthreads();

    if (tid < 128) {
        int r = tid & 63;
        const float* row = (tid < 64) ? &xs[r][0] : &ys[r][0];
        float s = 0.0f;
        #pragma unroll 8
        for (int k = 0; k < DH; k++) { float v = row[k]; s += v * v; }
        if (tid < 64) xn[r] = s; else yn[r] = s;
    }
    __syncthreads();

    int ty4 = (tid >> 4) * 4;
    int tx  = tid & 15;

    unsigned long long acc2[4][2] = {{0ull,0ull},{0ull,0ull},{0ull,0ull},{0ull,0ull}};

    #pragma unroll 4
    for (int k = 0; k < DH; k++) {
        float b0 = ys[tx     ][k];
        float b1 = ys[tx + 16][k];
        float b2 = ys[tx + 32][k];
        float b3 = ys[tx + 48][k];
        unsigned long long bp0 = pk2(b0, b1);
        unsigned long long bp1 = pk2(b2, b3);
        #pragma unroll
        for (int r = 0; r < 4; r++) {
            float a = xs[ty4 + r][k];
            unsigned long long ap = pk2(a, a);
            fma2(acc2[r][0], ap, bp0);
            fma2(acc2[r][1], ap, bp1);
        }
    }

    #pragma unroll
    for (int r = 0; r < 4; r++) {
        float xnr = xn[ty4 + r];
        #pragma unroll
        for (int cp = 0; cp < 2; cp++) {
            float v0, v1;
            upk2(acc2[r][cp], v0, v1);
            int c0 = tx + 16 * (2 * cp);
            int c1 = tx + 16 * (2 * cp + 1);
            Cs[ty4 + r][c0] = fmaxf(xnr + yn[c0] - 2.0f * v0, 0.0f);
            Cs[ty4 + r][c1] = fmaxf(xnr + yn[c1] - 2.0f * v1, 0.0f);
        }
    }
    __syncthreads();

    __half* outb = g_Ddiag + (size_t)b * (NDIAG * MM);
    int warp = tid >> 5, lane = tid & 31;
    for (int s = warp; s < 127; s += 8) {
        int lo = (s > 63) ? (s - 63) : 0;
        int hi = (s < 63) ? s : 63;
        __half* rp = outb + (unsigned)(i0 + j0 + s) * 512u + (unsigned)i0;
        for (int li = lo + lane; li <= hi; li += 32)
            rp[li] = __float2half_rn(Cs[li][s - li]);
    }
}

// ---------------------------------------------------------------------------
// Kernel 2: soft-DTW, barrier-free warp-pipelined wavefront.
// One CTA per batch, 256 threads (8 warps = 2 per SMSP), 2 rows/thread in
// registers. Depth-8 register prefetch ring for D. Cross-warp boundary value
// flows through full-length smem arrays (volatile store / poll).
// ---------------------------------------------------------------------------
__device__ __forceinline__ float cellv(float dg, float up, float lf,
                                       float D, int j)
{
    // softmin_gamma(dg, up, lf): sort3, exp(0)=1 -> 2x ex2 + 1x lg2
    float mn1 = fminf(dg, up), mx1 = fmaxf(dg, up);
    float m   = fminf(mn1, lf);
    float mid = fmaxf(fminf(mx1, lf), mn1);
    float mx  = fmaxf(mx1, lf);
    float mc  = m * SCALE_EX2;
    float e1  = ex2f(fmaf(mid, -SCALE_EX2, mc));
    float e2  = ex2f(fmaf(mx,  -SCALE_EX2, mc));
    float sum = 1.0f + e1 + e2;
    float r   = fmaf(-GLN2, lg2f(sum), m) + D;
    return ((unsigned)j <= (unsigned)(NN - 1)) ? r : BIGF;
}

__global__ __launch_bounds__(256) void dtw_kernel()
{
    __shared__ unsigned sm_bound[7][NDIAG];   // boundary c1 of warps 0..6

    int b = blockIdx.x;
    int t = threadIdx.x;
    int w = t >> 5, lane = t & 31;

    for (int e = t; e < 7 * NDIAG; e += 256)
        ((unsigned*)sm_bound)[e] = POISON;
    __syncthreads();   // only barrier in the kernel

    const __half* Db = g_Ddiag + (size_t)b * (NDIAG * MM) + 2 * t;
    const int i0   = 2 * t;            // this thread's top row (0-based)
    const int wlo  = w * 64;           // warp's first active diagonal
    const int whi  = wlo + 574;        // warp's last active diagonal
    const int pwhi = wlo + 510;        // last d-1 with a valid producer value

    float p1_0 = BIGF, p1_1 = BIGF;    // own rows at diagonal d-1
    float p2_0 = BIGF;                 // own top row at diagonal d-2
    float nb2 = (t == 0) ? 0.0f : BIGF;  // neighbor bottom row @ d-2 (seed C(-1,-1)=0)

    // Depth-8 prefetch ring (unsigned = 2 halves = this thread's 2 rows)
    unsigned pf[8];
    #pragma unroll
    for (int j = 0; j < 8; j++)
        pf[j] = *(const unsigned*)(Db + (unsigned)(wlo + j) * 512u);

    volatile unsigned* prod = (w > 0) ? &sm_bound[w - 1][0] : 0;

    for (int blk = 0; blk < 72; blk++) {
        int dbase = wlo + blk * 8;
        #pragma unroll
        for (int j = 0; j < 8; j++) {
            int d = dbase + j;
            if (d > whi) break;        // warp-uniform tail guard

            float nb1 = __shfl_up_sync(0xffffffffu, p1_1, 1);  // neighbor bottom @ d-1
            if (lane == 0) {
                if (w == 0 || d - 1 > pwhi) {
                    nb1 = BIGF;
                } else {
                    unsigned v = prod[d - 1];
                    while (v == POISON) v = prod[d - 1];   // producer runs ahead
                    nb1 = __uint_as_float(v);
                }
            }

            float2 dd = __half22float2(*(const __half2*)&pf[j]);

            float c0 = cellv(nb2,  nb1,  p1_0, dd.x, d - i0);
            float c1 = cellv(p2_0, p1_0, p1_1, dd.y, d - i0 - 1);

            if (w < 7 && lane == 31)
                ((volatile unsigned*)&sm_bound[w][d])[0] = __float_as_uint(c1);

            nb2 = nb1;
            p2_0 = p1_0;
            p1_0 = c0;  p1_1 = c1;

            int dn = d + 8;
            if (dn <= whi)
                pf[j] = *(const unsigned*)(Db + (unsigned)dn * 512u);
        }
    }

    if (t == 255) g_perbatch[b] = p1_1;   // C(511,511)
}

// ---------------------------------------------------------------------------
// Kernel 3: deterministic mean over batches.
// ---------------------------------------------------------------------------
__global__ void reduce_kernel(float* __restrict__ out)
{
    __shared__ float s[BATCH];
    s[threadIdx.x] = g_perbatch[threadIdx.x];
    __syncthreads();
    if (threadIdx.x == 0) {
        float acc = 0.0f;
        for (int i = 0; i < BATCH; i++) acc += s[i];
        out[0] = acc * (1.0f / BATCH);
    }
}

extern "C" void kernel_launch(void* const* d_in, const int* in_sizes, int n_in,
                              void* d_out, int out_size)
{
    const float* x = (const float*)d_in[0];
    const float* y = (const float*)d_in[1];
    float* out = (float*)d_out;

    dim3 g1(NN / 64, MM / 64, BATCH);
    pairwise_diag_kernel<<<g1, 256>>>(x, y);
    dtw_kernel<<<BATCH, 256>>>();
    reduce_kernel<<<1, BATCH>>>(out);
}

// round 10
// speedup vs baseline: 1.2492x; 1.2492x over previous
#include <cuda_runtime.h>
#include <cuda_fp16.h>

#define BATCH 64
#define MM 512
#define NN 512
#define DH 64
#define NDIAG (MM + NN - 1)   /* 1023 */
#define DIAGP 1040            /* padded diagonals per batch (unconditional prefetch) */
#define BIGF 1e10f
#define SCALE_EX2 14.4269504088896f   /* (1/gamma) * log2(e), gamma = 0.1 */
#define GLN2 0.0693147180559945f      /* gamma * ln(2) */
#define POISON 0x7FBFFFFFu            /* NaN pattern never produced by the DP */

// Diagonal-major distance matrix, fp16: Ddiag[b][(i+j)][i] = D[b][i][j]
__device__ __half g_Ddiag[(size_t)BATCH * DIAGP * MM];
__device__ float g_perbatch[BATCH];

__device__ __forceinline__ float ex2f(float x) {
    float r; asm("ex2.approx.ftz.f32 %0, %1;" : "=f"(r) : "f"(x)); return r;
}
__device__ __forceinline__ float lg2f(float x) {
    float r; asm("lg2.approx.ftz.f32 %0, %1;" : "=f"(r) : "f"(x)); return r;
}
__device__ __forceinline__ unsigned long long pk2(float lo, float hi) {
    unsigned long long p;
    asm("mov.b64 %0, {%1, %2};" : "=l"(p) : "f"(lo), "f"(hi));
    return p;
}
__device__ __forceinline__ void fma2(unsigned long long& acc,
                                     unsigned long long a, unsigned long long b) {
    asm("fma.rn.f32x2 %0, %1, %2, %0;" : "+l"(acc) : "l"(a), "l"(b));
}
__device__ __forceinline__ void upk2(unsigned long long p, float& lo, float& hi) {
    asm("mov.b64 {%0, %1}, %2;" : "=f"(lo), "=f"(hi) : "l"(p));
}

// ---------------------------------------------------------------------------
// Kernel 1: pairwise squared L2 -> diagonal-major fp16.  (proven, ~94us)
// ---------------------------------------------------------------------------
__global__ __launch_bounds__(256) void pairwise_diag_kernel(
    const float* __restrict__ x, const float* __restrict__ y)
{
    __shared__ float xs[64][65];
    __shared__ float ys[64][65];
    __shared__ float Cs[64][66];
    __shared__ float xn[64], yn[64];

    int b  = blockIdx.z;
    int i0 = blockIdx.y * 64;
    int j0 = blockIdx.x * 64;
    int tid = threadIdx.x;

    const float* xb = x + ((size_t)b * MM + i0) * DH;
    const float* yb = y + ((size_t)b * NN + j0) * DH;

    #pragma unroll
    for (int e = tid; e < 1024; e += 256) {
        int r = e >> 4, c = (e & 15) * 4;
        float4 vx = *(const float4*)&xb[r * DH + c];
        float4 vy = *(const float4*)&yb[r * DH + c];
        xs[r][c] = vx.x; xs[r][c+1] = vx.y; xs[r][c+2] = vx.z; xs[r][c+3] = vx.w;
        ys[r][c] = vy.x; ys[r][c+1] = vy.y; ys[r][c+2] = vy.z; ys[r][c+3] = vy.w;
    }
    __syncthreads();

    if (tid < 128) {
        int r = tid & 63;
        const float* row = (tid < 64) ? &xs[r][0] : &ys[r][0];
        float s = 0.0f;
        #pragma unroll 8
        for (int k = 0; k < DH; k++) { float v = row[k]; s += v * v; }
        if (tid < 64) xn[r] = s; else yn[r] = s;
    }
    __syncthreads();

    int ty4 = (tid >> 4) * 4;
    int tx  = tid & 15;

    unsigned long long acc2[4][2] = {{0ull,0ull},{0ull,0ull},{0ull,0ull},{0ull,0ull}};

    #pragma unroll 4
    for (int k = 0; k < DH; k++) {
        float b0 = ys[tx     ][k];
        float b1 = ys[tx + 16][k];
        float b2 = ys[tx + 32][k];
        float b3 = ys[tx + 48][k];
        unsigned long long bp0 = pk2(b0, b1);
        unsigned long long bp1 = pk2(b2, b3);
        #pragma unroll
        for (int r = 0; r < 4; r++) {
            float a = xs[ty4 + r][k];
            unsigned long long ap = pk2(a, a);
            fma2(acc2[r][0], ap, bp0);
            fma2(acc2[r][1], ap, bp1);
        }
    }

    #pragma unroll
    for (int r = 0; r < 4; r++) {
        float xnr = xn[ty4 + r];
        #pragma unroll
        for (int cp = 0; cp < 2; cp++) {
            float v0, v1;
            upk2(acc2[r][cp], v0, v1);
            int c0 = tx + 16 * (2 * cp);
            int c1 = tx + 16 * (2 * cp + 1);
            Cs[ty4 + r][c0] = fmaxf(xnr + yn[c0] - 2.0f * v0, 0.0f);
            Cs[ty4 + r][c1] = fmaxf(xnr + yn[c1] - 2.0f * v1, 0.0f);
        }
    }
    __syncthreads();

    __half* outb = g_Ddiag + (size_t)b * ((size_t)DIAGP * MM);
    int warp = tid >> 5, lane = tid & 31;
    for (int s = warp; s < 127; s += 8) {
        int lo = (s > 63) ? (s - 63) : 0;
        int hi = (s < 63) ? s : 63;
        __half* rp = outb + (unsigned)(i0 + j0 + s) * 512u + (unsigned)i0;
        for (int li = lo + lane; li <= hi; li += 32)
            rp[li] = __float2half_rn(Cs[li][s - li]);
    }
}

// ---------------------------------------------------------------------------
// Kernel 2: soft-DTW, branch-free warp-pipelined wavefront.
// One CTA per batch, 256 threads, 2 rows/thread in registers.
// - Boundary handoff: per-producer smem row, shifted by +1; never-written
//   slots pre-initialized to BIGF so ALL lanes do one uniform broadcast read
//   (SELP picks smem value for lane 0, shfl value otherwise). Retry loop is
//   warp-uniform (__any_sync) and never taken in steady state.
// - Boundary value for step d+1 is loaded during step d (LDS off-chain).
// - STS of own boundary is a predicated @p st.shared (no branch).
// - Exact trip counts, unconditional prefetch into padded g_Ddiag.
// ---------------------------------------------------------------------------
__device__ __forceinline__ float cellv(float dg, float up, float lf,
                                       float D, int j)
{
    // softmin_gamma(dg, up, lf): sort3, exp(0)=1 -> 2x ex2 + 1x lg2
    float mn1 = fminf(dg, up), mx1 = fmaxf(dg, up);
    float m   = fminf(mn1, lf);
    float mid = fmaxf(fminf(mx1, lf), mn1);
    float mx  = fmaxf(mx1, lf);
    float mc  = m * SCALE_EX2;
    float e1  = ex2f(fmaf(mid, -SCALE_EX2, mc));
    float e2  = ex2f(fmaf(mx,  -SCALE_EX2, mc));
    float sum = 1.0f + e1 + e2;
    float r   = fmaf(-GLN2, lg2f(sum), m) + D;
    return ((unsigned)j <= (unsigned)(NN - 1)) ? r : BIGF;
}

#define STEPBODY(DD, JJ, DOPF)                                               \
{                                                                            \
    const int d_ = (DD);                                                     \
    while (__any_sync(0xffffffffu, vcur == POISON))                          \
        vcur = ((volatile const unsigned*)prodrow)[d_];                      \
    float sh  = __shfl_up_sync(0xffffffffu, p1_1, 1);                        \
    float nb1 = (lane == 0) ? __uint_as_float(vcur) : sh;                    \
    float2 dd2 = pfv[JJ];                                                    \
    float c0 = cellv(nb2,  nb1,  p1_0, dd2.x, d_ - i0);                      \
    float c1 = cellv(p2_0, p1_0, p1_1, dd2.y, d_ - i0 - 1);                  \
    asm volatile("{ .reg .pred pq; setp.ne.u32 pq, %0, 0;\n\t"               \
                 "@pq st.shared.u32 [%1], %2; }"                             \
                 :: "r"(wflag), "r"(my_saddr + (unsigned)(d_ + 1) * 4u),     \
                    "r"(__float_as_uint(c1)) : "memory");                    \
    vcur = ((volatile const unsigned*)prodrow)[d_ + 1];                      \
    nb2 = nb1; p2_0 = p1_0; p1_0 = c0; p1_1 = c1;                            \
    if (DOPF) {                                                              \
        unsigned raw = *(const unsigned*)(Db + (unsigned)(d_ + 8) * 512u);   \
        pfv[JJ] = __half22float2(*(const __half2*)&raw);                     \
    }                                                                        \
}

__global__ __launch_bounds__(256) void dtw_kernel()
{
    __shared__ unsigned sm_bound[8][1024];

    int b = blockIdx.x;
    int t = threadIdx.x;
    int w = t >> 5, lane = t & 31;

    // Init: row r slots idx >= 64r+576 (read-but-never-written) and the whole
    // virtual row 7 (read by warp 0) = BIGF; everything else POISON.
    const unsigned BIGU = __float_as_uint(BIGF);
    #pragma unroll
    for (int e = t; e < 8 * 1024; e += 256) {
        int r = e >> 10, idx = e & 1023;
        ((unsigned*)sm_bound)[e] = (r == 7 || idx >= 64 * r + 576) ? BIGU : POISON;
    }
    __syncthreads();   // only barrier in the kernel

    const __half* Db = g_Ddiag + (size_t)b * ((size_t)DIAGP * MM) + 2 * t;
    const int i0  = 2 * t;            // this thread's top row
    const int wlo = w * 64;           // warp's first active diagonal (575 steps)

    float p1_0 = BIGF, p1_1 = BIGF;   // own rows at diagonal d-1
    float p2_0 = BIGF;                // own top row at diagonal d-2
    float nb2 = (t == 0) ? 0.0f : BIGF;  // neighbor bottom @ d-2 (C(-1,-1)=0 seed)

    // Depth-8 prefetch ring, converted to float2 at load time.
    float2 pfv[8];
    #pragma unroll
    for (int j = 0; j < 8; j++) {
        unsigned raw = *(const unsigned*)(Db + (unsigned)(wlo + j) * 512u);
        pfv[j] = __half22float2(*(const __half2*)&raw);
    }

    const unsigned* prodrow = &sm_bound[(w + 7) & 7][0];
    unsigned my_saddr = (unsigned)__cvta_generic_to_shared(&sm_bound[w][0]);
    int wflag = (w < 7) && (lane == 31);

    unsigned vcur = ((volatile const unsigned*)prodrow)[wlo];

    int d = wlo;
    for (int blk = 0; blk < 71; blk++) {        // 71 x 8 = 568 steps
        STEPBODY(d + 0, 0, 1)
        STEPBODY(d + 1, 1, 1)
        STEPBODY(d + 2, 2, 1)
        STEPBODY(d + 3, 3, 1)
        STEPBODY(d + 4, 4, 1)
        STEPBODY(d + 5, 5, 1)
        STEPBODY(d + 6, 6, 1)
        STEPBODY(d + 7, 7, 1)
        d += 8;
    }
    // remainder: 7 steps (no prefetch) -> 575 total
    STEPBODY(d + 0, 0, 0)
    STEPBODY(d + 1, 1, 0)
    STEPBODY(d + 2, 2, 0)
    STEPBODY(d + 3, 3, 0)
    STEPBODY(d + 4, 4, 0)
    STEPBODY(d + 5, 5, 0)
    STEPBODY(d + 6, 6, 0)

    if (t == 255) g_perbatch[b] = p1_1;   // C(511,511)
}

// ---------------------------------------------------------------------------
// Kernel 3: deterministic mean over batches.
// ---------------------------------------------------------------------------
__global__ void reduce_kernel(float* __restrict__ out)
{
    __shared__ float s[BATCH];
    s[threadIdx.x] = g_perbatch[threadIdx.x];
    __syncthreads();
    if (threadIdx.x == 0) {
        float acc = 0.0f;
        for (int i = 0; i < BATCH; i++) acc += s[i];
        out[0] = acc * (1.0f / BATCH);
    }
}

extern "C" void kernel_launch(void* const* d_in, const int* in_sizes, int n_in,
                              void* d_out, int out_size)
{
    const float* x = (const float*)d_in[0];
    const float* y = (const float*)d_in[1];
    float* out = (float*)d_out;

    dim3 g1(NN / 64, MM / 64, BATCH);
    pairwise_diag_kernel<<<g1, 256>>>(x, y);
    dtw_kernel<<<BATCH, 256>>>();
    reduce_kernel<<<1, BATCH>>>(out);
}